// round 2
// baseline (speedup 1.0000x reference)
#include <cuda_runtime.h>
#include <cuda_bf16.h>
#include <cstdint>

// Problem constants
#define TT 500
#define BB 32
#define INF 512
#define HH 1024
#define G4 4096
#define H2 2048

// Scratch: gx for both directions: 2 * 500 * 32 * 4096 floats = 524 MB
__device__ float g_gx[(size_t)2 * TT * BB * G4];
// Cell state: [dir][b][j]
__device__ float g_c[2 * BB * HH];

__device__ __forceinline__ float hsig(float x) {
    return fminf(fmaxf(0.2f * x + 0.5f, 0.0f), 1.0f);
}
__device__ __forceinline__ float htanh(float x) {
    return fminf(fmaxf(x, -1.0f), 1.0f);
}

// ---------------------------------------------------------------------------
// Kernel 1: gx[dir][m][g] = sum_i x[m][i] * w_ih[g][i] + b_ih[g] + b_hh[g]
// M = T*B = 16000, N = 4096, K = 512. Tiles: 64x64x16, 256 threads, 4x4/thread.
// ---------------------------------------------------------------------------
__global__ void gemm_gx_kernel(const float* __restrict__ x,
                               const float* __restrict__ wih_f,
                               const float* __restrict__ wih_r,
                               const float* __restrict__ bih_f,
                               const float* __restrict__ bhh_f,
                               const float* __restrict__ bih_r,
                               const float* __restrict__ bhh_r) {
    const int dir = blockIdx.z;
    const float* __restrict__ w  = dir ? wih_r : wih_f;
    const float* __restrict__ b1 = dir ? bih_r : bih_f;
    const float* __restrict__ b2 = dir ? bhh_r : bhh_f;
    float* __restrict__ gx = g_gx + (size_t)dir * TT * BB * G4;

    const int m0 = blockIdx.y * 64;
    const int n0 = blockIdx.x * 64;

    __shared__ float As[16][64];  // [kk][mm]
    __shared__ float Bs[16][64];  // [kk][nn]

    const int tid = threadIdx.x;
    const int tx = tid & 15;        // 0..15 (n)
    const int ty = tid >> 4;        // 0..15 (m)

    float acc[4][4] = {};

    for (int k0 = 0; k0 < INF; k0 += 16) {
        // Load A tile (x) and B tile (w), 64 rows x 16 k each, transposed to smem.
        {
            const int row = tid >> 2;     // 0..63
            const int kq  = tid & 3;      // 0..3 (float4 within 16 k)
            float4 va = *(const float4*)&x[(size_t)(m0 + row) * INF + k0 + kq * 4];
            As[kq * 4 + 0][row] = va.x;
            As[kq * 4 + 1][row] = va.y;
            As[kq * 4 + 2][row] = va.z;
            As[kq * 4 + 3][row] = va.w;
            float4 vb = *(const float4*)&w[(size_t)(n0 + row) * INF + k0 + kq * 4];
            Bs[kq * 4 + 0][row] = vb.x;
            Bs[kq * 4 + 1][row] = vb.y;
            Bs[kq * 4 + 2][row] = vb.z;
            Bs[kq * 4 + 3][row] = vb.w;
        }
        __syncthreads();
        #pragma unroll
        for (int kk = 0; kk < 16; ++kk) {
            float4 a = *(float4*)&As[kk][ty * 4];
            float4 bb = *(float4*)&Bs[kk][tx * 4];
            float av[4] = {a.x, a.y, a.z, a.w};
            float bv[4] = {bb.x, bb.y, bb.z, bb.w};
            #pragma unroll
            for (int i = 0; i < 4; ++i)
                #pragma unroll
                for (int j = 0; j < 4; ++j)
                    acc[i][j] = fmaf(av[i], bv[j], acc[i][j]);
        }
        __syncthreads();
    }

    #pragma unroll
    for (int i = 0; i < 4; ++i) {
        const int m = m0 + ty * 4 + i;
        #pragma unroll
        for (int j = 0; j < 4; ++j) {
            const int n = n0 + tx * 4 + j;
            gx[(size_t)m * G4 + n] = acc[i][j] + b1[n] + b2[n];
        }
    }
}

// ---------------------------------------------------------------------------
// Kernel 2: one recurrent step for both directions.
// grid = (64 j-tiles, 2 dirs), block = 256 threads (8 warps).
// Block handles 16 hidden units j (=> 64 gate rows), all 32 batches.
// Warp w handles j in {j0+2w, j0+2w+1}; lane = batch b.
// h history lives inside `out`:
//   forward h_prev(t)  = out[t-1][b][0:H]
//   reverse h_prev(s)  = out[tr+1][b][H:2H]   (tr = T-1-s)
// ---------------------------------------------------------------------------
__global__ void lstm_step_kernel(const float* __restrict__ whh_f,
                                 const float* __restrict__ whh_r,
                                 float* __restrict__ out, int t) {
    const int dir = blockIdx.y;
    const float* __restrict__ whh = dir ? whh_r : whh_f;
    const float* __restrict__ gx = g_gx + (size_t)dir * TT * BB * G4;
    const int j0 = blockIdx.x * 16;
    const int tr = dir ? (TT - 1 - t) : t;

    const int tid = threadIdx.x;
    const int lane = tid & 31;  // batch
    const int w = tid >> 5;     // warp -> j pair

    __shared__ float ws[64][32];   // 64 gate rows x 32 k chunk
    __shared__ float hs[32][36];   // 32 batches x 32 k chunk (padded, 16B-aligned rows)

    float acc[2][4] = {};

    const float* hprev = nullptr;
    if (t > 0) {
        const int hp_t = dir ? (tr + 1) : (t - 1);
        hprev = out + (size_t)hp_t * BB * H2 + dir * HH;
    }

    for (int k0 = 0; k0 < HH; k0 += 32) {
        // Load weight tile: 64 rows (jj*4+gate) x 32 k => 512 float4, 2/thread
        #pragma unroll
        for (int l = 0; l < 2; ++l) {
            const int idx = tid + l * 256;
            const int r = idx >> 3;        // 0..63
            const int q = idx & 7;         // float4 index in chunk
            const int jj = r >> 2;
            const int gate = r & 3;
            const float* src = whh + (size_t)(gate * HH + j0 + jj) * HH + k0 + q * 4;
            *(float4*)&ws[r][q * 4] = *(const float4*)src;
        }
        // Load h chunk: 32 b x 32 k => 256 float4, 1/thread
        {
            const int bb = tid >> 3;
            const int q = tid & 7;
            float4 v = make_float4(0.f, 0.f, 0.f, 0.f);
            if (t > 0) v = *(const float4*)&hprev[(size_t)bb * H2 + k0 + q * 4];
            *(float4*)&hs[bb][q * 4] = v;
        }
        __syncthreads();

        #pragma unroll
        for (int k4 = 0; k4 < 8; ++k4) {
            float4 hv = *(float4*)&hs[lane][k4 * 4];
            #pragma unroll
            for (int jj2 = 0; jj2 < 2; ++jj2) {
                const int rbase = (2 * w + jj2) * 4;
                #pragma unroll
                for (int g = 0; g < 4; ++g) {
                    float4 wv = *(float4*)&ws[rbase + g][k4 * 4];
                    float a = acc[jj2][g];
                    a = fmaf(hv.x, wv.x, a);
                    a = fmaf(hv.y, wv.y, a);
                    a = fmaf(hv.z, wv.z, a);
                    a = fmaf(hv.w, wv.w, a);
                    acc[jj2][g] = a;
                }
            }
        }
        __syncthreads();
    }

    // Finalize: apply gx + nonlinearity + cell update, write h into out.
    #pragma unroll
    for (int jj2 = 0; jj2 < 2; ++jj2) {
        const int jj = 2 * w + jj2;
        const int j = j0 + jj;
        const size_t gxbase = ((size_t)tr * BB + lane) * G4 + j;
        const float gi = acc[jj2][0] + gx[gxbase];
        const float gf = acc[jj2][1] + gx[gxbase + HH];
        const float gc = acc[jj2][2] + gx[gxbase + 2 * HH];
        const float go = acc[jj2][3] + gx[gxbase + 3 * HH];

        const float i_ = hsig(gi);
        const float f_ = hsig(gf);
        const float c_ = htanh(gc);
        const float o_ = hsig(go);

        const size_t cidx = ((size_t)dir * BB + lane) * HH + j;
        const float cp = (t == 0) ? 0.0f : g_c[cidx];
        const float cn = f_ * cp + i_ * c_;
        g_c[cidx] = cn;
        const float h = o_ * htanh(cn);
        out[((size_t)tr * BB + lane) * H2 + dir * HH + j] = h;
    }
}

// ---------------------------------------------------------------------------
// Kernel 3: write hy, cy into the output tail.
// Layout: out = [ output (T*B*2H) | hy (2*B*H) | cy (2*B*H) ]
// ---------------------------------------------------------------------------
__global__ void finalize_kernel(float* __restrict__ out) {
    const int idx = blockIdx.x * blockDim.x + threadIdx.x;  // 0..65535
    const int j = idx & (HH - 1);
    const int b = (idx >> 10) & (BB - 1);
    const int dir = idx >> 15;

    const size_t base = (size_t)TT * BB * H2;
    float h;
    if (dir == 0)
        h = out[((size_t)(TT - 1) * BB + b) * H2 + j];           // forward final = out[T-1][:, :H]
    else
        h = out[((size_t)b) * H2 + HH + j];                      // reverse final = out[0][:, H:]
    out[base + ((size_t)dir * BB + b) * HH + j] = h;
    out[base + 2 * BB * HH + ((size_t)dir * BB + b) * HH + j] =
        g_c[((size_t)dir * BB + b) * HH + j];
}

// ---------------------------------------------------------------------------
extern "C" void kernel_launch(void* const* d_in, const int* in_sizes, int n_in,
                              void* d_out, int out_size) {
    const float* x     = (const float*)d_in[0];
    const float* wih_f = (const float*)d_in[1];
    const float* whh_f = (const float*)d_in[2];
    const float* bih_f = (const float*)d_in[3];
    const float* bhh_f = (const float*)d_in[4];
    const float* wih_r = (const float*)d_in[5];
    const float* whh_r = (const float*)d_in[6];
    const float* bih_r = (const float*)d_in[7];
    const float* bhh_r = (const float*)d_in[8];
    float* out = (float*)d_out;

    // Phase 1: time-parallel input GEMM (both directions).
    dim3 ggrid(G4 / 64, (TT * BB) / 64, 2);  // (64, 250, 2)
    gemm_gx_kernel<<<ggrid, 256>>>(x, wih_f, wih_r, bih_f, bhh_f, bih_r, bhh_r);

    // Phase 2: 500 sequential recurrent steps (both directions per launch).
    for (int t = 0; t < TT; ++t)
        lstm_step_kernel<<<dim3(64, 2), 256>>>(whh_f, whh_r, out, t);

    // Phase 3: hy / cy tail.
    finalize_kernel<<<64, 1024>>>(out);
}

// round 3
// speedup vs baseline: 1.4550x; 1.4550x over previous
#include <cuda_runtime.h>
#include <cstdint>

// Problem constants
#define TT 500
#define BB 32
#define INF 512
#define HH 1024
#define G4 4096
#define H2 2048

#define NBLK 148
#define NWARP 14
#define NTHR 448
#define KP 512        // k-pairs (K=1024 packed in 2s)
#define CHKP 64       // k-pairs per chunk
#define NCH 8         // chunks per step

// gx in recurrence-friendly layout: [dir][t][j][gate][b]
__device__ float g_gxp[(size_t)2 * TT * HH * 4 * BB];
// packed recurrent weights: [dir][j][kp][gate][2]
__device__ float g_wpk[(size_t)2 * HH * KP * 8];
// h ping buffer: [dir][kp][b][2]  (32768 floats per dir)
__device__ float g_ht[2 * KP * BB * 2];
// grid barrier counter
__device__ unsigned g_count;

__device__ __forceinline__ float hsig(float x) {
    return fminf(fmaxf(0.2f * x + 0.5f, 0.0f), 1.0f);
}
__device__ __forceinline__ float htanh(float x) {
    return fminf(fmaxf(x, -1.0f), 1.0f);
}

__device__ __forceinline__ void fma2(unsigned long long& acc,
                                     unsigned long long a,
                                     unsigned long long b) {
    asm volatile("fma.rn.f32x2 %0, %1, %2, %0;" : "+l"(acc) : "l"(a), "l"(b));
}
__device__ __forceinline__ float2 unpk(unsigned long long v) {
    float2 r;
    asm("mov.b64 {%0, %1}, %2;" : "=f"(r.x), "=f"(r.y) : "l"(v));
    return r;
}
__device__ __forceinline__ uint32_t smaddr(const void* p) {
    uint32_t a;
    asm("{ .reg .u64 t; cvta.to.shared.u64 t, %1; cvt.u32.u64 %0, t; }"
        : "=r"(a) : "l"(p));
    return a;
}
__device__ __forceinline__ void cpa16(uint32_t s, const void* g) {
    asm volatile("cp.async.cg.shared.global [%0], [%1], 16;" :: "r"(s), "l"(g));
}
__device__ __forceinline__ void cpa_commit() {
    asm volatile("cp.async.commit_group;");
}
template <int N>
__device__ __forceinline__ void cpa_wait() {
    asm volatile("cp.async.wait_group %0;" :: "n"(N));
}

// ---------------------------------------------------------------------------
// Prepack w_hh -> [dir][j][kp][gate][2]
// thread id -> (dir, j, kp); writes 8 floats, reads 4 float2.
// ---------------------------------------------------------------------------
__global__ void prepack_kernel(const float* __restrict__ whh_f,
                               const float* __restrict__ whh_r) {
    const int id = blockIdx.x * blockDim.x + threadIdx.x;   // 0 .. 2*1024*512-1
    const int dir = id >> 19;
    const int j = (id >> 9) & 1023;
    const int kp = id & 511;
    const float* w = dir ? whh_r : whh_f;
    float out[8];
#pragma unroll
    for (int g = 0; g < 4; ++g) {
        float2 v = *(const float2*)&w[(size_t)(g * HH + j) * HH + 2 * kp];
        out[g * 2 + 0] = v.x;
        out[g * 2 + 1] = v.y;
    }
    float* dst = g_wpk + ((size_t)(dir * HH + j) * KP + kp) * 8;
    *(float4*)dst = *(float4*)out;
    *(float4*)(dst + 4) = *(float4*)(out + 4);
}

// ---------------------------------------------------------------------------
// Zero ht + barrier counter.
// ---------------------------------------------------------------------------
__global__ void init_kernel() {
    const int id = blockIdx.x * blockDim.x + threadIdx.x;
    if (id < 2 * KP * BB * 2) g_ht[id] = 0.0f;
    if (id == 0) g_count = 0u;
}

// ---------------------------------------------------------------------------
// Input GEMM: gxp[dir][t][j][g][b] = x[t,b,:] . w_ih[g*H+j,:] + b_ih + b_hh
// M = T*B = 16000, N = 4096, K = 512. 64x64x16 tiles, 256 thr, 4x4/thread.
// ---------------------------------------------------------------------------
__global__ void gemm_gx_kernel(const float* __restrict__ x,
                               const float* __restrict__ wih_f,
                               const float* __restrict__ wih_r,
                               const float* __restrict__ bih_f,
                               const float* __restrict__ bhh_f,
                               const float* __restrict__ bih_r,
                               const float* __restrict__ bhh_r) {
    const int dir = blockIdx.z;
    const float* __restrict__ w  = dir ? wih_r : wih_f;
    const float* __restrict__ b1 = dir ? bih_r : bih_f;
    const float* __restrict__ b2 = dir ? bhh_r : bhh_f;
    float* __restrict__ gx = g_gxp + (size_t)dir * TT * HH * 4 * BB;

    const int m0 = blockIdx.y * 64;
    const int n0 = blockIdx.x * 64;

    __shared__ float As[16][64];
    __shared__ float Bs[16][64];

    const int tid = threadIdx.x;
    const int tx = tid & 15;
    const int ty = tid >> 4;

    float acc[4][4] = {};

    for (int k0 = 0; k0 < INF; k0 += 16) {
        {
            const int row = tid >> 2;
            const int kq  = tid & 3;
            float4 va = *(const float4*)&x[(size_t)(m0 + row) * INF + k0 + kq * 4];
            As[kq * 4 + 0][row] = va.x;
            As[kq * 4 + 1][row] = va.y;
            As[kq * 4 + 2][row] = va.z;
            As[kq * 4 + 3][row] = va.w;
            float4 vb = *(const float4*)&w[(size_t)(n0 + row) * INF + k0 + kq * 4];
            Bs[kq * 4 + 0][row] = vb.x;
            Bs[kq * 4 + 1][row] = vb.y;
            Bs[kq * 4 + 2][row] = vb.z;
            Bs[kq * 4 + 3][row] = vb.w;
        }
        __syncthreads();
#pragma unroll
        for (int kk = 0; kk < 16; ++kk) {
            float4 a = *(float4*)&As[kk][ty * 4];
            float4 bb = *(float4*)&Bs[kk][tx * 4];
            float av[4] = {a.x, a.y, a.z, a.w};
            float bv[4] = {bb.x, bb.y, bb.z, bb.w};
#pragma unroll
            for (int i = 0; i < 4; ++i)
#pragma unroll
                for (int jn = 0; jn < 4; ++jn)
                    acc[i][jn] = fmaf(av[i], bv[jn], acc[i][jn]);
        }
        __syncthreads();
    }

    // Store to [t][j][g][b] layout, vectorized along b.
    const int mbase = m0 + ty * 4;      // 4 consecutive m = same t, 4 consecutive b
    const int t = mbase >> 5;
    const int b0 = mbase & 31;
#pragma unroll
    for (int jn = 0; jn < 4; ++jn) {
        const int n = n0 + tx * 4 + jn;
        const int gate = n >> 10;
        const int jj = n & 1023;
        const float bias = b1[n] + b2[n];
        float4 v = make_float4(acc[0][jn] + bias, acc[1][jn] + bias,
                               acc[2][jn] + bias, acc[3][jn] + bias);
        *(float4*)&gx[(((size_t)t * HH + jj) * 4 + gate) * BB + b0] = v;
    }
}

// ---------------------------------------------------------------------------
// Persistent recurrence kernel. 148 blocks x 448 threads (14 warps).
// Warp = one hidden unit j (all 4 gates, lane = batch). c in registers.
// smem: w chunks [2][14][64][8] (2x28KB) + h chunks [2][64][32][2] (2x16KB).
// ---------------------------------------------------------------------------
__global__ void __launch_bounds__(NTHR, 1)
lstm_persistent(float* __restrict__ out) {
    extern __shared__ float sm[];
    float* wsm = sm;                 // 2 * 7168 floats
    float* hsm = sm + 2 * 7168;      // 2 * 4096 floats

    const int tid = threadIdx.x;
    const int lane = tid & 31;
    const int wid = tid >> 5;
    const int bid = blockIdx.x;
    const int dir = (bid >= 74) ? 1 : 0;
    const int db = dir ? bid - 74 : bid;
    const int j_lo = (db * HH) / 74;
    const int j_hi = ((db + 1) * HH) / 74;
    const int nj = j_hi - j_lo;          // 13 or 14
    const int j = j_lo + wid;
    const bool active = (wid < nj);

    const int ht_dir = dir * (KP * BB * 2);           // float offset
    const float* __restrict__ gxd = g_gxp + (size_t)dir * TT * HH * 4 * BB;
    const float* __restrict__ wdir = g_wpk + (size_t)dir * HH * KP * 8;

    float c = 0.0f;
    float h_fin = 0.0f;

    for (int t = 0; t < TT; ++t) {
        const int tr = dir ? (TT - 1 - t) : t;

        // chunk loader (all threads)
        auto load_chunk = [&](int ck, int buf) {
            const int kp0 = ck * CHKP;
            const int nwu = nj * 128;            // 16B units of weights
            for (int u = tid; u < nwu; u += NTHR) {
                const int jl = u >> 7;
                const int r = u & 127;
                const int kp = r >> 1;
                const int half = r & 1;
                const float* g = wdir + ((size_t)(j_lo + jl) * KP + kp0 + kp) * 8 + half * 4;
                cpa16(smaddr(wsm + buf * 7168 + jl * 512 + kp * 8 + half * 4), g);
            }
            const float* hg = g_ht + ht_dir + kp0 * 64;
            for (int u = tid; u < 1024; u += NTHR) {
                cpa16(smaddr(hsm + buf * 4096 + u * 4), hg + u * 4);
            }
        };

        load_chunk(0, 0); cpa_commit();
        load_chunk(1, 1); cpa_commit();

        unsigned long long acc0 = 0ULL, acc1 = 0ULL, acc2 = 0ULL, acc3 = 0ULL;

        for (int ck = 0; ck < NCH; ++ck) {
            cpa_wait<1>();
            __syncthreads();
            const int buf = ck & 1;
            if (active) {
                const float* wb = wsm + buf * 7168 + wid * 512;
                const float* hb = hsm + buf * 4096;
#pragma unroll 8
                for (int kp = 0; kp < CHKP; ++kp) {
                    unsigned long long hp =
                        *(const unsigned long long*)(hb + (kp * BB + lane) * 2);
                    const float* wk = wb + kp * 8;
                    ulonglong2 wA = *(const ulonglong2*)(wk);
                    ulonglong2 wB = *(const ulonglong2*)(wk + 4);
                    fma2(acc0, wA.x, hp);
                    fma2(acc1, wA.y, hp);
                    fma2(acc2, wB.x, hp);
                    fma2(acc3, wB.y, hp);
                }
            }
            __syncthreads();
            if (ck + 2 < NCH) load_chunk(ck + 2, buf);
            cpa_commit();
        }

        if (active) {
            const size_t gb = (((size_t)tr * HH + j) * 4) * BB + lane;
            float2 a0 = unpk(acc0), a1 = unpk(acc1), a2 = unpk(acc2), a3 = unpk(acc3);
            const float gi = a0.x + a0.y + gxd[gb];
            const float gf = a1.x + a1.y + gxd[gb + 32];
            const float gc = a2.x + a2.y + gxd[gb + 64];
            const float go = a3.x + a3.y + gxd[gb + 96];
            const float i_ = hsig(gi);
            const float f_ = hsig(gf);
            const float cg = htanh(gc);
            const float o_ = hsig(go);
            c = f_ * c + i_ * cg;
            const float h = o_ * htanh(c);
            h_fin = h;
            out[((size_t)tr * BB + lane) * H2 + dir * HH + j] = h;
            g_ht[ht_dir + (j >> 1) * 64 + lane * 2 + (j & 1)] = h;
        }

        // grid-wide barrier
        __threadfence();
        __syncthreads();
        if (tid == 0) {
            atomicAdd(&g_count, 1u);
            const unsigned target = (unsigned)NBLK * (unsigned)(t + 1);
            volatile unsigned* p = &g_count;
            while (*p < target) __nanosleep(64);
            __threadfence();
        }
        __syncthreads();
    }

    if (active) {
        const size_t base = (size_t)TT * BB * H2;
        out[base + ((size_t)dir * BB + lane) * HH + j] = h_fin;
        out[base + 2 * BB * HH + ((size_t)dir * BB + lane) * HH + j] = c;
    }
}

// ---------------------------------------------------------------------------
extern "C" void kernel_launch(void* const* d_in, const int* in_sizes, int n_in,
                              void* d_out, int out_size) {
    const float* x     = (const float*)d_in[0];
    const float* wih_f = (const float*)d_in[1];
    const float* whh_f = (const float*)d_in[2];
    const float* bih_f = (const float*)d_in[3];
    const float* bhh_f = (const float*)d_in[4];
    const float* wih_r = (const float*)d_in[5];
    const float* whh_r = (const float*)d_in[6];
    const float* bih_r = (const float*)d_in[7];
    const float* bhh_r = (const float*)d_in[8];
    float* out = (float*)d_out;

    const int smem_bytes = (2 * 7168 + 2 * 4096) * 4;   // 90112
    cudaFuncSetAttribute(lstm_persistent,
                         cudaFuncAttributeMaxDynamicSharedMemorySize, smem_bytes);

    prepack_kernel<<<2048, 512>>>(whh_f, whh_r);
    init_kernel<<<66, 1024>>>();
    dim3 ggrid(G4 / 64, (TT * BB) / 64, 2);
    gemm_gx_kernel<<<ggrid, 256>>>(x, wih_f, wih_r, bih_f, bhh_f, bih_r, bhh_r);
    lstm_persistent<<<NBLK, NTHR, smem_bytes>>>(out);
}